// round 17
// baseline (speedup 1.0000x reference)
#include <cuda_runtime.h>
#include <cuda_bf16.h>

// out[n, d] = dist[n] * w[d]   (N = 1,000,000 rows, DIM = 256, fp32)
// R16: R15 champion (UNROLL=16 deep store bursts, grid-stride interleave,
// __stcs streaming STG.128, 1184 CTAs) with 32-bit indexing to cut the
// per-address register cost (64-bit IADD3.X pairs -> single adds).
// Goal: regs 64 -> ~52 so 5 CTAs/SM fit instead of 4, raising aggregate
// outstanding stores per SM ~25% at the same burst depth. No forced
// launch-bounds cap (forcing 32 regs measured slower in R8).

#define DIM 256
#define VEC4_PER_ROW (DIM / 4)   // 64
#define TPB 256
#define NBLK 1184                // 148 SMs; back-fill scheduling as CTAs drain
#define UNROLL 16

__global__ __launch_bounds__(TPB) void outer_product_persistent(
    const float* __restrict__ dist,
    const float* __restrict__ weight,
    float4* __restrict__ out,
    unsigned total_vec4)         // n_rows * 64 = 64M < 2^32
{
    // Fixed column for this thread (grid stride is a multiple of 64).
    const int col4 = threadIdx.x & (VEC4_PER_ROW - 1);
    const float4 w = __ldg(&reinterpret_cast<const float4*>(weight)[col4]);

    const unsigned stride = NBLK * TPB;          // 303104, multiple of 64
    unsigned i = blockIdx.x * TPB + threadIdx.x;

    // Main loop: 16 interleaved rows per iteration. Front-batch the
    // (warp-uniform) dist loads, then compute+store each element
    // immediately so register live ranges stay short.
    for (; i + (UNROLL - 1) * stride < total_vec4; i += UNROLL * stride) {
        float d[UNROLL];
#pragma unroll
        for (int j = 0; j < UNROLL; j++) {
            d[j] = __ldg(&dist[(i + j * stride) >> 6]);
        }
#pragma unroll
        for (int j = 0; j < UNROLL; j++) {
            float4 r;
            r.x = d[j] * w.x;
            r.y = d[j] * w.y;
            r.z = d[j] * w.z;
            r.w = d[j] * w.w;
            __stcs(&out[i + j * stride], r);   // evict-first streaming store
        }
    }

    // Tail.
    for (; i < total_vec4; i += stride) {
        const float dd = __ldg(&dist[i >> 6]);
        float4 r;
        r.x = dd * w.x; r.y = dd * w.y; r.z = dd * w.z; r.w = dd * w.w;
        __stcs(&out[i], r);
    }
}

extern "C" void kernel_launch(void* const* d_in, const int* in_sizes, int n_in,
                              void* d_out, int out_size)
{
    const float* dist   = (const float*)d_in[0];
    const float* weight = (const float*)d_in[1];
    float4* out         = (float4*)d_out;

    unsigned total_vec4 = (unsigned)in_sizes[0] * VEC4_PER_ROW;  // 64M

    outer_product_persistent<<<NBLK, TPB>>>(dist, weight, out, total_vec4);
}